// round 2
// baseline (speedup 1.0000x reference)
#include <cuda_runtime.h>

#define B_  1024
#define N_  128
#define H_  128
#define FE_ 8
#define G3_ 384      // 3*H
#define KX_ 136      // H+FE

// device scratch (no cudaMalloc allowed)
__device__ __align__(16) float g_hs[B_ * H_];        // per-batch sum of h over N
__device__ __align__(16) float g_bias[B_ * G3_];     // per-batch gate bias (message part + b_ih [+ b_hh])
__device__ __align__(16) float g_WT[H_ * G3_];       // WT[k][g] = W_hh[g][k]

// ---------------- K0: transpose W_hh [384,128] -> WT [128,384] ----------------
__global__ void k_transpose(const float* __restrict__ Whh) {
    int idx = blockIdx.x * 256 + threadIdx.x;
    if (idx < G3_ * H_) {
        int g = idx / H_, k = idx % H_;
        g_WT[k * G3_ + g] = Whh[idx];
    }
}

// ---------------- K1: hs[b,k] = sum_n h[b,n,k] ----------------
__global__ void k_rowsum(const float* __restrict__ h) {
    int b = blockIdx.x;
    int k = threadIdx.x;
    const float* p = h + (size_t)b * N_ * H_ + k;
    float s0 = 0.f, s1 = 0.f, s2 = 0.f, s3 = 0.f;
    #pragma unroll 8
    for (int n = 0; n < N_; n += 4) {
        s0 += p[(n + 0) * H_];
        s1 += p[(n + 1) * H_];
        s2 += p[(n + 2) * H_];
        s3 += p[(n + 3) * H_];
    }
    g_hs[b * H_ + k] = (s0 + s1) + (s2 + s3);
}

// ---------------- K2: per-batch message + gate bias ----------------
// message[b,k] = tanh(hs[b]·Wm[k,:] + N*bm[k])
// bias[b,g]    = message[b]·W_ih[g,0:128] + b_ih[g] + (g<256 ? b_hh[g] : 0)
__global__ void k_bias(const float* __restrict__ Wm, const float* __restrict__ bm,
                       const float* __restrict__ Wih, const float* __restrict__ bih,
                       const float* __restrict__ bhh) {
    __shared__ float hsS[H_];
    __shared__ float msgS[H_];
    int b = blockIdx.x;
    int k = threadIdx.x;

    hsS[k] = g_hs[b * H_ + k];
    __syncthreads();

    const float4* wr = (const float4*)(Wm + (size_t)k * H_);
    float d = 0.f;
    #pragma unroll
    for (int j = 0; j < H_ / 4; j++) {
        float4 w = wr[j];
        d += hsS[4 * j + 0] * w.x + hsS[4 * j + 1] * w.y
           + hsS[4 * j + 2] * w.z + hsS[4 * j + 3] * w.w;
    }
    msgS[k] = tanhf(d + (float)N_ * bm[k]);
    __syncthreads();

    #pragma unroll
    for (int q = 0; q < 3; q++) {
        int g = q * H_ + k;
        const float4* wi = (const float4*)(Wih + (size_t)g * KX_);  // 136*4 bytes = 16B-aligned rows
        float d2 = 0.f;
        #pragma unroll
        for (int j = 0; j < H_ / 4; j++) {
            float4 w = wi[j];
            d2 += msgS[4 * j + 0] * w.x + msgS[4 * j + 1] * w.y
                + msgS[4 * j + 2] * w.z + msgS[4 * j + 3] * w.w;
        }
        float bias = d2 + bih[g];
        if (g < 2 * H_) bias += bhh[g];
        g_bias[b * G3_ + g] = bias;
    }
}

// ---------------- K3: fused GEMM (h·W_hh^T, jets·W_ih_jets^T) + GRU epilogue ----------------
// Tile: 32 rows x 384 gate-cols per CTA. 256 threads: (tr=tid/32 -> 4 rows each, tg=tid%32 -> 4 g each).
// smem (floats):
//   As    [32][132]   h tile (padded)
//   jetsS [32][8]
//   WjSt  [8][384]    WjSt[f][g] = W_ih[g][128+f]
//   biasS [384]
//   bhhnS [128]       b_hh[256+g]
//   Ws    [32][388]   K-chunk of WT (padded)
__global__ void __launch_bounds__(256, 2) k_main(
    const float* __restrict__ h, const float* __restrict__ jets,
    const float* __restrict__ Wih, const float* __restrict__ bhh,
    float* __restrict__ out)
{
    extern __shared__ float sm[];
    float* As    = sm;                      // 4224
    float* jetsS = As + 32 * 132;           // 256
    float* WjSt  = jetsS + 32 * 8;          // 3072
    float* biasS = WjSt + 8 * 384;          // 384
    float* bhhnS = biasS + 384;             // 128
    float* Ws    = bhhnS + 128;             // 12416

    const int tid = threadIdx.x;
    const int m0  = blockIdx.x * 32;
    const int b   = m0 >> 7;                // 4 CTAs per batch row-group

    // load h tile -> As (coalesced float4)
    {
        const float4* h4 = (const float4*)(h + (size_t)m0 * H_);
        #pragma unroll
        for (int t = tid; t < 32 * 32; t += 256) {
            int row = t >> 5, c4 = t & 31;
            *(float4*)&As[row * 132 + c4 * 4] = h4[t];
        }
    }
    // jets tile
    {
        const float4* j4 = (const float4*)(jets + (size_t)m0 * FE_);
        if (tid < 64) *(float4*)&jetsS[tid * 4] = j4[tid];
    }
    // WjSt[f][g] = Wih[g][128+f]
    for (int g = tid; g < G3_; g += 256) {
        const float* src = Wih + (size_t)g * KX_ + H_;
        float4 a4 = *(const float4*)(src);
        float4 b4 = *(const float4*)(src + 4);
        WjSt[0 * G3_ + g] = a4.x; WjSt[1 * G3_ + g] = a4.y;
        WjSt[2 * G3_ + g] = a4.z; WjSt[3 * G3_ + g] = a4.w;
        WjSt[4 * G3_ + g] = b4.x; WjSt[5 * G3_ + g] = b4.y;
        WjSt[6 * G3_ + g] = b4.z; WjSt[7 * G3_ + g] = b4.w;
    }
    for (int g = tid; g < G3_; g += 256) biasS[g] = g_bias[b * G3_ + g];
    if (tid < 128) bhhnS[tid] = bhh[256 + tid];

    const int tr = tid >> 5;
    const int tg = tid & 31;
    const int gb = tg * 4;

    float acc0[4][4] = {};   // r:  h·W_hh_r + jets·W_ih_r
    float acc1[4][4] = {};   // z:  h·W_hh_z + jets·W_ih_z
    float acc2[4][4] = {};   // hn: h·W_hh_n
    float accN[4][4] = {};   // in: jets·W_ih_n (message+bias part in biasS)

    for (int kc = 0; kc < H_; kc += 32) {
        __syncthreads();   // protect Ws from overwrite while prior chunk in use
        #pragma unroll
        for (int t = tid; t < 32 * 96; t += 256) {   // 32 k-rows x 96 float4
            int kk = t / 96, c4 = t % 96;
            float4 v = ((const float4*)g_WT)[(kc + kk) * 96 + c4];
            *(float4*)&Ws[kk * 388 + c4 * 4] = v;
        }
        __syncthreads();

        #pragma unroll
        for (int k4 = 0; k4 < 32; k4 += 4) {
            float4 av[4];
            #pragma unroll
            for (int i = 0; i < 4; i++)
                av[i] = *(const float4*)&As[(tr * 4 + i) * 132 + kc + k4];
            #pragma unroll
            for (int kk = 0; kk < 4; kk++) {
                const float4 w0 = *(const float4*)&Ws[(k4 + kk) * 388 + gb];
                const float4 w1 = *(const float4*)&Ws[(k4 + kk) * 388 + 128 + gb];
                const float4 w2 = *(const float4*)&Ws[(k4 + kk) * 388 + 256 + gb];
                #pragma unroll
                for (int i = 0; i < 4; i++) {
                    float a = (kk == 0) ? av[i].x : (kk == 1) ? av[i].y
                            : (kk == 2) ? av[i].z : av[i].w;
                    acc0[i][0] += a * w0.x; acc0[i][1] += a * w0.y;
                    acc0[i][2] += a * w0.z; acc0[i][3] += a * w0.w;
                    acc1[i][0] += a * w1.x; acc1[i][1] += a * w1.y;
                    acc1[i][2] += a * w1.z; acc1[i][3] += a * w1.w;
                    acc2[i][0] += a * w2.x; acc2[i][1] += a * w2.y;
                    acc2[i][2] += a * w2.z; acc2[i][3] += a * w2.w;
                }
            }
        }
    }

    // jets (K=8) contribution
    #pragma unroll
    for (int f = 0; f < 8; f++) {
        const float4 wr = *(const float4*)&WjSt[f * G3_ + gb];
        const float4 wz = *(const float4*)&WjSt[f * G3_ + 128 + gb];
        const float4 wn = *(const float4*)&WjSt[f * G3_ + 256 + gb];
        #pragma unroll
        for (int i = 0; i < 4; i++) {
            float jf = jetsS[(tr * 4 + i) * 8 + f];
            acc0[i][0] += jf * wr.x; acc0[i][1] += jf * wr.y;
            acc0[i][2] += jf * wr.z; acc0[i][3] += jf * wr.w;
            acc1[i][0] += jf * wz.x; acc1[i][1] += jf * wz.y;
            acc1[i][2] += jf * wz.z; acc1[i][3] += jf * wz.w;
            accN[i][0] += jf * wn.x; accN[i][1] += jf * wn.y;
            accN[i][2] += jf * wn.z; accN[i][3] += jf * wn.w;
        }
    }

    // GRU epilogue + store
    const float4 bR4 = *(const float4*)&biasS[gb];
    const float4 bZ4 = *(const float4*)&biasS[128 + gb];
    const float4 bN4 = *(const float4*)&biasS[256 + gb];
    const float4 bH4 = *(const float4*)&bhhnS[gb];
    #pragma unroll
    for (int i = 0; i < 4; i++) {
        int row = tr * 4 + i;
        float4 hv = *(const float4*)&As[row * 132 + gb];
        float o[4];
        #pragma unroll
        for (int j = 0; j < 4; j++) {
            float br = ((const float*)&bR4)[j];
            float bz = ((const float*)&bZ4)[j];
            float bn = ((const float*)&bN4)[j];
            float bh = ((const float*)&bH4)[j];
            float hj = ((const float*)&hv)[j];
            float r = 1.f / (1.f + __expf(-(acc0[i][j] + br)));
            float z = 1.f / (1.f + __expf(-(acc1[i][j] + bz)));
            float n = tanhf(accN[i][j] + bn + r * (acc2[i][j] + bh));
            o[j] = (1.f - z) * n + z * hj;
        }
        *(float4*)(out + (size_t)(m0 + row) * H_ + gb) = make_float4(o[0], o[1], o[2], o[3]);
    }
}

extern "C" void kernel_launch(void* const* d_in, const int* in_sizes, int n_in,
                              void* d_out, int out_size) {
    const float* h    = (const float*)d_in[0];
    const float* jets = (const float*)d_in[1];
    // d_in[2] = mask (unused by reference forward)
    const float* Wm   = (const float*)d_in[3];
    const float* bm   = (const float*)d_in[4];
    const float* Wih  = (const float*)d_in[5];
    const float* Whh  = (const float*)d_in[6];
    const float* bih  = (const float*)d_in[7];
    const float* bhh  = (const float*)d_in[8];
    float* out = (float*)d_out;

    // 80 KB dynamic smem for k_main (idempotent; not a stream op, capture-safe)
    const int smem_bytes = (32 * 132 + 32 * 8 + 8 * 384 + 384 + 128 + 32 * 388) * 4;  // 81920
    cudaFuncSetAttribute(k_main, cudaFuncAttributeMaxDynamicSharedMemorySize, smem_bytes);

    k_transpose<<<(G3_ * H_ + 255) / 256, 256>>>(Whh);
    k_rowsum<<<B_, H_>>>(h);
    k_bias<<<B_, H_>>>(Wm, bm, Wih, bih, bhh);
    k_main<<<(B_ * N_) / 32, 256, smem_bytes>>>(h, jets, Wih, bhh, out);
}

// round 4
// speedup vs baseline: 1.3559x; 1.3559x over previous
#include <cuda_runtime.h>
#include <cuda_bf16.h>
#include <cstdint>

#define B_  1024
#define N_  128
#define H_  128
#define FE_ 8
#define G3_ 384
#define KX_ 136
#define KP_ 152          // padded K stride in elements (304 bytes, conflict-free)
#define KSTEPS 9         // K = 144 (128 h + 8 jets + 8 zero)

// ---------------- device scratch ----------------
__device__ __align__(16) float g_hs[B_ * H_];
__device__ __align__(16) float g_bias[B_ * G3_];
__device__ __align__(16) __nv_bfloat16 g_Bhi[G3_ * KP_];
__device__ __align__(16) __nv_bfloat16 g_Blo[G3_ * KP_];

__device__ __forceinline__ uint32_t pack_bf2(float a, float b) {
    __nv_bfloat16 ah = __float2bfloat16(a), bh = __float2bfloat16(b);
    return (uint32_t)__bfloat16_as_ushort(ah) | ((uint32_t)__bfloat16_as_ushort(bh) << 16);
}
__device__ __forceinline__ uint32_t pack_bf2_res(float a, float b) {
    __nv_bfloat16 ah = __float2bfloat16(a), bh = __float2bfloat16(b);
    float ar = a - __bfloat162float(ah), br = b - __bfloat162float(bh);
    return (uint32_t)__bfloat16_as_ushort(__float2bfloat16(ar))
         | ((uint32_t)__bfloat16_as_ushort(__float2bfloat16(br)) << 16);
}
__device__ __forceinline__ float bf_lo(uint32_t u) {
    return __bfloat162float(__ushort_as_bfloat16((unsigned short)(u & 0xffff)));
}
__device__ __forceinline__ float bf_hi(uint32_t u) {
    return __bfloat162float(__ushort_as_bfloat16((unsigned short)(u >> 16)));
}

#define MMA16816(ac, a0, a1, a2, a3, b0, b1)                                   \
    asm volatile("mma.sync.aligned.m16n8k16.row.col.f32.bf16.bf16.f32 "        \
                 "{%0,%1,%2,%3}, {%4,%5,%6,%7}, {%8,%9}, {%0,%1,%2,%3};"       \
                 : "+f"((ac)[0]), "+f"((ac)[1]), "+f"((ac)[2]), "+f"((ac)[3])  \
                 : "r"(a0), "r"(a1), "r"(a2), "r"(a3), "r"(b0), "r"(b1))

// ---------------- prep: W_hh (+jets cols of W_ih) -> bf16 hi/lo, padded [384][152] ----------------
__global__ void k_prep(const float* __restrict__ Whh, const float* __restrict__ Wih) {
    int i = blockIdx.x * 256 + threadIdx.x;
    if (i >= G3_ * KP_) return;
    int g = i / KP_, k = i % KP_;
    float w = 0.f;
    if (k < H_) w = Whh[g * H_ + k];
    else if (k < H_ + FE_ && g < 2 * H_) w = Wih[(size_t)g * KX_ + k];  // jets weights for r,z only
    __nv_bfloat16 hi = __float2bfloat16(w);
    g_Bhi[i] = hi;
    g_Blo[i] = __float2bfloat16(w - __bfloat162float(hi));
}

// ---------------- rowsum: hs[b] = sum_n h[b,n,:] ----------------
__global__ void k_rowsum(const float* __restrict__ h) {
    __shared__ float4 red[256];
    int b = blockIdx.x, tid = threadIdx.x;
    int k4 = tid & 31, n0 = tid >> 5;
    const float4* p = (const float4*)(h + (size_t)b * N_ * H_) + k4;
    float4 s = make_float4(0.f, 0.f, 0.f, 0.f);
    #pragma unroll
    for (int j = 0; j < 16; j++) {
        float4 v = p[(size_t)(n0 + 8 * j) * 32];
        s.x += v.x; s.y += v.y; s.z += v.z; s.w += v.w;
    }
    red[tid] = s;
    __syncthreads();
    #pragma unroll
    for (int off = 128; off >= 32; off >>= 1) {
        if (tid < off) {
            float4 a = red[tid], c = red[tid + off];
            a.x += c.x; a.y += c.y; a.z += c.z; a.w += c.w;
            red[tid] = a;
        }
        __syncthreads();
    }
    if (tid < 32) ((float4*)g_hs)[b * 32 + tid] = red[tid];
}

// ---------------- bias: per-batch message + gate bias ----------------
__global__ void k_bias(const float* __restrict__ Wm, const float* __restrict__ bm,
                       const float* __restrict__ Wih, const float* __restrict__ bih,
                       const float* __restrict__ bhh) {
    __shared__ float hsS[H_];
    __shared__ float msgS[H_];
    int b = blockIdx.x;
    int k = threadIdx.x;
    hsS[k] = g_hs[b * H_ + k];
    __syncthreads();
    const float4* wr = (const float4*)(Wm + (size_t)k * H_);
    float d = 0.f;
    #pragma unroll
    for (int j = 0; j < H_ / 4; j++) {
        float4 w = wr[j];
        d += hsS[4 * j + 0] * w.x + hsS[4 * j + 1] * w.y
           + hsS[4 * j + 2] * w.z + hsS[4 * j + 3] * w.w;
    }
    msgS[k] = tanhf(d + (float)N_ * bm[k]);
    __syncthreads();
    #pragma unroll
    for (int q = 0; q < 3; q++) {
        int g = q * H_ + k;
        const float4* wi = (const float4*)(Wih + (size_t)g * KX_);
        float d2 = 0.f;
        #pragma unroll
        for (int j = 0; j < H_ / 4; j++) {
            float4 w = wi[j];
            d2 += msgS[4 * j + 0] * w.x + msgS[4 * j + 1] * w.y
                + msgS[4 * j + 2] * w.z + msgS[4 * j + 3] * w.w;
        }
        float bias = d2 + bih[g];
        if (g < 2 * H_) bias += bhh[g];   // fold b_hh into r,z bias; n-gate b_hh kept separate
        g_bias[b * G3_ + g] = bias;
    }
}

// ---------------- smem layout for k_main (bytes) ----------------
#define OFF_B    0            // 116736  B [384][152] bf16 (hi, then reloaded as lo)
#define OFF_AH   116736       //  38912  A_hi [128][152] bf16
#define OFF_AL   155648       //  38912  A_lo
#define OFF_JET  194560       //   4096  jets fp32 [128][8]
#define OFF_WJN  198656       //   4096  W_ih n-gate jets cols fp32 [128][8]
#define OFF_BIAS 202752       //   1536
#define OFF_BHHN 204288       //    512
#define SMEM_SZ  204800

// ---------------- main: HMMA split-precision GEMM + GRU epilogue ----------------
__global__ void __launch_bounds__(256, 1) k_main(
    const float* __restrict__ h, const float* __restrict__ jets,
    const float* __restrict__ Wih, const float* __restrict__ bhh,
    float* __restrict__ out)
{
    extern __shared__ char smem[];
    const int tid  = threadIdx.x;
    const int wid  = tid >> 5;
    const int lane = tid & 31;
    const int cta  = blockIdx.x;   // one batch per CTA

    // ---- stage B_hi ----
    {
        const uint4* src = (const uint4*)g_Bhi;
        uint4* dst = (uint4*)(smem + OFF_B);
        for (int i = tid; i < G3_ * KP_ * 2 / 16; i += 256) dst[i] = src[i];
    }
    // ---- convert h -> A_hi/A_lo ----
    {
        const float4* hp = (const float4*)(h + (size_t)cta * 128 * 128);
        for (int i = tid; i < 4096; i += 256) {
            int row = i >> 5, q = i & 31;
            float4 v = hp[i];
            uint2 hi2 = make_uint2(pack_bf2(v.x, v.y), pack_bf2(v.z, v.w));
            uint2 lo2 = make_uint2(pack_bf2_res(v.x, v.y), pack_bf2_res(v.z, v.w));
            *(uint2*)(smem + OFF_AH + row * 304 + q * 8) = hi2;
            *(uint2*)(smem + OFF_AL + row * 304 + q * 8) = lo2;
        }
    }
    // ---- jets (A cols 128..151 + fp32 copies), W_jn, bhh_n ----
    if (tid < 128) {
        int row = tid;
        const float4* jp = (const float4*)(jets + (size_t)(cta * 128 + row) * FE_);
        float4 j0 = jp[0], j1 = jp[1];
        *(float4*)(smem + OFF_JET + row * 32)      = j0;
        *(float4*)(smem + OFF_JET + row * 32 + 16) = j1;
        uint4 jh = make_uint4(pack_bf2(j0.x, j0.y), pack_bf2(j0.z, j0.w),
                              pack_bf2(j1.x, j1.y), pack_bf2(j1.z, j1.w));
        uint4 jl = make_uint4(pack_bf2_res(j0.x, j0.y), pack_bf2_res(j0.z, j0.w),
                              pack_bf2_res(j1.x, j1.y), pack_bf2_res(j1.z, j1.w));
        uint4 zz = make_uint4(0, 0, 0, 0);
        *(uint4*)(smem + OFF_AH + row * 304 + 256) = jh;
        *(uint4*)(smem + OFF_AH + row * 304 + 272) = zz;
        *(uint4*)(smem + OFF_AH + row * 304 + 288) = zz;
        *(uint4*)(smem + OFF_AL + row * 304 + 256) = jl;
        *(uint4*)(smem + OFF_AL + row * 304 + 272) = zz;
        *(uint4*)(smem + OFF_AL + row * 304 + 288) = zz;
        const float4* wp = (const float4*)(Wih + (size_t)(2 * H_ + row) * KX_ + H_);
        *(float4*)(smem + OFF_WJN + row * 32)      = wp[0];
        *(float4*)(smem + OFF_WJN + row * 32 + 16) = wp[1];
        ((float*)(smem + OFF_BHHN))[row] = bhh[2 * H_ + row];
    }
    for (int g = tid; g < G3_; g += 256)
        ((float*)(smem + OFF_BIAS))[g] = g_bias[cta * G3_ + g];
    __syncthreads();

    // ---- 3-pass MMA: A_hi*B_hi, A_lo*B_hi, A_hi*B_lo ----
    float acc[48][4];
    #pragma unroll
    for (int t = 0; t < 48; t++) {
        acc[t][0] = 0.f; acc[t][1] = 0.f; acc[t][2] = 0.f; acc[t][3] = 0.f;
    }

    const uint32_t aByte = (uint32_t)(wid * 16 + (lane >> 2)) * 304 + (lane & 3) * 4;
    const uint32_t bByte = (uint32_t)(lane >> 2) * 304 + (lane & 3) * 4;

    #pragma unroll 1
    for (int pass = 0; pass < 3; pass++) {
        if (pass == 2) {   // uniform across CTA
            __syncthreads();
            const uint4* src = (const uint4*)g_Blo;
            uint4* dst = (uint4*)(smem + OFF_B);
            for (int i = tid; i < G3_ * KP_ * 2 / 16; i += 256) dst[i] = src[i];
            __syncthreads();
        }
        const char* Ab = smem + ((pass == 1) ? OFF_AL : OFF_AH) + aByte;
        #pragma unroll 1
        for (int ks = 0; ks < KSTEPS; ks++) {
            uint32_t a0 = *(const uint32_t*)(Ab + ks * 32);
            uint32_t a1 = *(const uint32_t*)(Ab + ks * 32 + 2432);
            uint32_t a2 = *(const uint32_t*)(Ab + ks * 32 + 16);
            uint32_t a3 = *(const uint32_t*)(Ab + ks * 32 + 2448);
            const char* Bb = smem + OFF_B + bByte + ks * 32;
            #pragma unroll
            for (int nt = 0; nt < 48; nt++) {
                uint32_t b0 = *(const uint32_t*)(Bb + nt * 2432);
                uint32_t b1 = *(const uint32_t*)(Bb + nt * 2432 + 16);
                MMA16816(acc[nt], a0, a1, a2, a3, b0, b1);
            }
        }
    }

    // ---- GRU epilogue ----
    {
        const float* biasS = (const float*)(smem + OFF_BIAS);
        const float* bhhnS = (const float*)(smem + OFF_BHHN);
        const int r0 = wid * 16 + (lane >> 2);
        const int r1 = r0 + 8;
        const int cb = (lane & 3) * 2;
        float j0[8], j1[8];
        {
            float4 a = *(const float4*)(smem + OFF_JET + r0 * 32);
            float4 b = *(const float4*)(smem + OFF_JET + r0 * 32 + 16);
            j0[0]=a.x; j0[1]=a.y; j0[2]=a.z; j0[3]=a.w; j0[4]=b.x; j0[5]=b.y; j0[6]=b.z; j0[7]=b.w;
            a = *(const float4*)(smem + OFF_JET + r1 * 32);
            b = *(const float4*)(smem + OFF_JET + r1 * 32 + 16);
            j1[0]=a.x; j1[1]=a.y; j1[2]=a.z; j1[3]=a.w; j1[4]=b.x; j1[5]=b.y; j1[6]=b.z; j1[7]=b.w;
        }
        const size_t mBase = (size_t)cta * 128;
        #pragma unroll
        for (int t = 0; t < 16; t++) {
            const int c = t * 8 + cb;
            float4 w0a = *(const float4*)(smem + OFF_WJN + c * 32);
            float4 w0b = *(const float4*)(smem + OFF_WJN + c * 32 + 16);
            float4 w1a = *(const float4*)(smem + OFF_WJN + (c + 1) * 32);
            float4 w1b = *(const float4*)(smem + OFF_WJN + (c + 1) * 32 + 16);
            uint32_t hh0 = *(const uint32_t*)(smem + OFF_AH + r0 * 304 + c * 2);
            uint32_t hl0 = *(const uint32_t*)(smem + OFF_AL + r0 * 304 + c * 2);
            uint32_t hh1 = *(const uint32_t*)(smem + OFF_AH + r1 * 304 + c * 2);
            uint32_t hl1 = *(const uint32_t*)(smem + OFF_AL + r1 * 304 + c * 2);
            float o[2][2];
            #pragma unroll
            for (int rw = 0; rw < 2; rw++) {
                const float* jv = rw ? j1 : j0;
                #pragma unroll
                for (int e = 0; e < 2; e++) {
                    int g = c + e;
                    float aR = acc[t][rw * 2 + e];
                    float aZ = acc[t + 16][rw * 2 + e];
                    float aN = acc[t + 32][rw * 2 + e];
                    float4 wa = e ? w1a : w0a;
                    float4 wb = e ? w1b : w0b;
                    float jd = jv[0] * wa.x + jv[1] * wa.y + jv[2] * wa.z + jv[3] * wa.w
                             + jv[4] * wb.x + jv[5] * wb.y + jv[6] * wb.z + jv[7] * wb.w;
                    float r = 1.f / (1.f + __expf(-(aR + biasS[g])));
                    float z = 1.f / (1.f + __expf(-(aZ + biasS[128 + g])));
                    float n = tanhf(jd + biasS[256 + g] + r * (aN + bhhnS[g]));
                    uint32_t hhv = rw ? hh1 : hh0, hlv = rw ? hl1 : hl0;
                    float hv = (e ? bf_hi(hhv) : bf_lo(hhv)) + (e ? bf_hi(hlv) : bf_lo(hlv));
                    o[rw][e] = (1.f - z) * n + z * hv;
                }
            }
            *(float2*)(out + (mBase + r0) * 128 + c) = make_float2(o[0][0], o[0][1]);
            *(float2*)(out + (mBase + r1) * 128 + c) = make_float2(o[1][0], o[1][1]);
        }
    }
}

extern "C" void kernel_launch(void* const* d_in, const int* in_sizes, int n_in,
                              void* d_out, int out_size) {
    const float* h    = (const float*)d_in[0];
    const float* jets = (const float*)d_in[1];
    // d_in[2] = mask (unused)
    const float* Wm   = (const float*)d_in[3];
    const float* bm   = (const float*)d_in[4];
    const float* Wih  = (const float*)d_in[5];
    const float* Whh  = (const float*)d_in[6];
    const float* bih  = (const float*)d_in[7];
    const float* bhh  = (const float*)d_in[8];
    float* out = (float*)d_out;

    cudaFuncSetAttribute(k_main, cudaFuncAttributeMaxDynamicSharedMemorySize, SMEM_SZ);

    k_prep<<<(G3_ * KP_ + 255) / 256, 256>>>(Whh, Wih);
    k_rowsum<<<B_, 256>>>(h);
    k_bias<<<B_, H_>>>(Wm, bm, Wih, bih, bhh);
    k_main<<<B_, 256, SMEM_SZ>>>(h, jets, Wih, bhh, out);
}